// round 16
// baseline (speedup 1.0000x reference)
#include <cuda_runtime.h>
#include <cuda_bf16.h>
#include <math.h>
#include <stdint.h>

#define BB 4
#define SS 1024
#define DD 512
#define HH 8
#define DH 64
#define RH 64
#define L2E 1.44269504f

// ---------------- static device scratch ----------------
__device__ __nv_bfloat16 g_Q[BB*HH*SS*DH];   // 4 MB (pre-scaled 1/8 * log2e)
__device__ __nv_bfloat16 g_K[BB*HH*SS*DH];   // 4 MB
__device__ __nv_bfloat16 g_Vt[BB*HH*DH*SS];  // 4 MB [b,h,d,s] (written directly by qkv)
__device__ __nv_bfloat16 g_featH[BB*SS*RH];
__device__ __nv_bfloat16 g_biasH[(size_t)BB*HH*SS*SS]; // 64 MB (bias * log2e)
__device__ float g_ctx[BB*SS*DD];        // tf32-rounded bits
__device__ float g_Wt[4*DD*DD];          // tf32-rounded W^T
__device__ float g_part[2*BB*SS*DD];     // 16 MB split-K partials

// ---------------- helpers ----------------
static __device__ __forceinline__ uint32_t f2t(float x) {
    uint32_t r; asm("cvt.rna.tf32.f32 %0, %1;" : "=r"(r) : "f"(x)); return r;
}
static __device__ __forceinline__ float ex2f(float x) {
    float y; asm("ex2.approx.ftz.f32 %0, %1;" : "=f"(y) : "f"(x)); return y;
}
static __device__ __forceinline__ uint32_t su32(const void* p) {
    uint32_t a;
    asm("{ .reg .u64 t; cvta.to.shared.u64 t, %1; cvt.u32.u64 %0, t; }" : "=r"(a) : "l"(p));
    return a;
}
static __device__ __forceinline__ void cp16(uint32_t dst, const void* src) {
    asm volatile("cp.async.ca.shared.global [%0], [%1], 16;" :: "r"(dst), "l"(src) : "memory");
}
#define CP_COMMIT() asm volatile("cp.async.commit_group;" ::: "memory")
#define CP_WAIT0()  asm volatile("cp.async.wait_group 0;" ::: "memory")
#define CP_WAIT1()  asm volatile("cp.async.wait_group 1;" ::: "memory")

static __device__ __forceinline__ void ldsm_x4(
    uint32_t& r0, uint32_t& r1, uint32_t& r2, uint32_t& r3, uint32_t addr)
{
    asm volatile("ldmatrix.sync.aligned.m8n8.x4.shared.b16 {%0,%1,%2,%3}, [%4];"
                 : "=r"(r0), "=r"(r1), "=r"(r2), "=r"(r3) : "r"(addr));
}

static __device__ __forceinline__ void mma_tf32(
    float* c, uint32_t a0, uint32_t a1, uint32_t a2, uint32_t a3,
    uint32_t b0, uint32_t b1)
{
    asm volatile(
        "mma.sync.aligned.m16n8k8.row.col.f32.tf32.tf32.f32 "
        "{%0,%1,%2,%3}, {%4,%5,%6,%7}, {%8,%9}, {%0,%1,%2,%3};"
        : "+f"(c[0]), "+f"(c[1]), "+f"(c[2]), "+f"(c[3])
        : "r"(a0), "r"(a1), "r"(a2), "r"(a3), "r"(b0), "r"(b1));
}
static __device__ __forceinline__ void mma_bf16(
    float* c, uint32_t a0, uint32_t a1, uint32_t a2, uint32_t a3,
    uint32_t b0, uint32_t b1)
{
    asm volatile(
        "mma.sync.aligned.m16n8k16.row.col.f32.bf16.bf16.f32 "
        "{%0,%1,%2,%3}, {%4,%5,%6,%7}, {%8,%9}, {%0,%1,%2,%3};"
        : "+f"(c[0]), "+f"(c[1]), "+f"(c[2]), "+f"(c[3])
        : "r"(a0), "r"(a1), "r"(a2), "r"(a3), "r"(b0), "r"(b1));
}

// ---------------- tf32 HMMA GEMM core: BM=128, BK=32, 2-stage cp.async (73728 B) ------
// vmode: 0 = head-split bf16 (Q/K), 1 = transposed bf16 V, 2 = fp32 + bias, 3 = fp32 raw
#define LDA2 36

__device__ __forceinline__ void hmma_gemm_core(
    uint32_t* __restrict__ dynsm,
    const uint32_t* __restrict__ A, const uint32_t* __restrict__ Wt,
    const float* __restrict__ bias, __nv_bfloat16* __restrict__ OutHalf,
    float hscale, float* __restrict__ OutPlain, int vmode, int bx, int by, int kiters)
{
    uint32_t* As = dynsm;                    // 2 * 128 * LDA2
    uint32_t* Bs = dynsm + 2 * 128 * LDA2;   // 2 * 128 * LDA2

    const int tid = threadIdx.x;
    const int lane = tid & 31;
    const int warp = tid >> 5;
    const int wm = warp >> 2, wn = warp & 3;
    const int m0 = by * 128, n0 = bx * 128;

    const int grow = tid >> 1;
    const int gk = (tid & 1) * 16;
    const uint32_t* Arow = A + (size_t)(m0 + grow) * DD + gk;
    const uint32_t* Brow = Wt + (size_t)(n0 + grow) * DD + gk;

    const uint32_t a_sb = su32(As);
    const uint32_t b_sb = a_sb + 2 * 128 * LDA2 * 4;
    const uint32_t soff = ((uint32_t)grow * LDA2 + gk) * 4;

#define GSTAGE(k0, buf) do { \
    uint32_t o_ = (uint32_t)(buf) * (128 * LDA2 * 4) + soff; \
    cp16(a_sb + o_,      Arow + (k0)); \
    cp16(a_sb + o_ + 16, Arow + (k0) + 4); \
    cp16(a_sb + o_ + 32, Arow + (k0) + 8); \
    cp16(a_sb + o_ + 48, Arow + (k0) + 12); \
    cp16(b_sb + o_,      Brow + (k0)); \
    cp16(b_sb + o_ + 16, Brow + (k0) + 4); \
    cp16(b_sb + o_ + 32, Brow + (k0) + 8); \
    cp16(b_sb + o_ + 48, Brow + (k0) + 12); \
    CP_COMMIT(); \
} while (0)

    float c[4][4][4];
#pragma unroll
    for (int mt = 0; mt < 4; ++mt)
#pragma unroll
        for (int nt = 0; nt < 4; ++nt)
#pragma unroll
            for (int i = 0; i < 4; ++i) c[mt][nt][i] = 0.f;

    const int am = wm * 64 + (lane >> 2);
    const int ak = lane & 3;
    const int bn = wn * 32 + (lane >> 2);

    GSTAGE(0, 0);
    GSTAGE(32, 1);

    for (int it = 0; it < kiters; ++it) {
        int buf = it & 1;
        if (it < kiters - 1) CP_WAIT1(); else CP_WAIT0();
        __syncthreads();
        const uint32_t* as = As + buf * 128 * LDA2;
        const uint32_t* bs = Bs + buf * 128 * LDA2;
#pragma unroll
        for (int ks = 0; ks < 4; ++ks) {
            int k0 = ks * 8;
            uint32_t bf[4][2];
#pragma unroll
            for (int nt = 0; nt < 4; ++nt) {
                bf[nt][0] = bs[(bn + nt * 8) * LDA2 + k0 + ak];
                bf[nt][1] = bs[(bn + nt * 8) * LDA2 + k0 + ak + 4];
            }
#pragma unroll
            for (int mt = 0; mt < 4; ++mt) {
                uint32_t a0 = as[(am + mt * 16) * LDA2 + k0 + ak];
                uint32_t a1 = as[(am + mt * 16 + 8) * LDA2 + k0 + ak];
                uint32_t a2 = as[(am + mt * 16) * LDA2 + k0 + ak + 4];
                uint32_t a3 = as[(am + mt * 16 + 8) * LDA2 + k0 + ak + 4];
#pragma unroll
                for (int nt = 0; nt < 4; ++nt)
                    mma_tf32(c[mt][nt], a0, a1, a2, a3, bf[nt][0], bf[nt][1]);
            }
        }
        __syncthreads();
        if (it + 2 < kiters) GSTAGE((it + 2) * 32, buf);
    }

    const int crow = lane >> 2;
    const int ccol = (lane & 3) * 2;
#pragma unroll
    for (int mt = 0; mt < 4; ++mt) {
#pragma unroll
        for (int nt = 0; nt < 4; ++nt) {
            int gcol = n0 + wn * 32 + nt * 8 + ccol;
            float bxv = (vmode == 3) ? 0.f : bias[gcol];
            float byv = (vmode == 3) ? 0.f : bias[gcol + 1];
#pragma unroll
            for (int half = 0; half < 2; ++half) {
                int m = m0 + wm * 64 + mt * 16 + crow + half * 8;
                float ox = c[mt][nt][half * 2 + 0] + bxv;
                float oy = c[mt][nt][half * 2 + 1] + byv;
                if (vmode == 0) {
                    int bidx = m >> 10, srow = m & 1023;
                    int h = gcol >> 6, d0 = gcol & 63;
                    __nv_bfloat162 ob = __floats2bfloat162_rn(ox * hscale, oy * hscale);
                    *(uint32_t*)(OutHalf + (((size_t)bidx * HH + h) * SS + srow) * DH + d0) =
                        *(uint32_t*)&ob;
                } else if (vmode == 1) {
                    int bidx = m >> 10, srow = m & 1023;
                    int h = gcol >> 6, d0 = gcol & 63;
                    __nv_bfloat16* base = OutHalf + ((size_t)(bidx * HH + h) * DH + d0) * SS;
                    base[srow]      = __float2bfloat16(ox);
                    base[SS + srow] = __float2bfloat16(oy);
                } else {
                    *(float2*)(OutPlain + (size_t)m * DD + gcol) = make_float2(ox, oy);
                }
            }
        }
    }
#undef GSTAGE
}

// ---------------- bias core: 16 i-rows per block (2 per warp); W2,b2 scaled by log2e --
#define LJS 72
__device__ __forceinline__ void bias_core(
    __nv_bfloat16* __restrict__ gjs,
    const float* __restrict__ b1, const float* __restrict__ W2, const float* __restrict__ b2,
    int b, int i0)   // i0 multiple of 16
{
    __shared__ __nv_bfloat16 gib_s[16][64];

    const int tid = threadIdx.x;
    const int lane = tid & 31;
    const int w = tid >> 5;
    const int r0 = lane >> 2;
    const int cc = lane & 3;

    for (int l = tid; l < 1024; l += 256) {
        int wi = l >> 6, k = l & 63;
        float gv = __bfloat162float(g_featH[((size_t)b * SS + i0 + wi) * RH + k]) + b1[k];
        gib_s[wi][k] = __float2bfloat16(gv);
    }

    uint32_t wb[4][2];
#pragma unroll
    for (int s = 0; s < 4; ++s) {
        __nv_bfloat162 p0 = __floats2bfloat162_rn(W2[(16 * s + 2 * cc) * HH + r0] * L2E,
                                                  W2[(16 * s + 2 * cc + 1) * HH + r0] * L2E);
        __nv_bfloat162 p1 = __floats2bfloat162_rn(W2[(16 * s + 2 * cc + 8) * HH + r0] * L2E,
                                                  W2[(16 * s + 2 * cc + 9) * HH + r0] * L2E);
        wb[s][0] = *(uint32_t*)&p0;
        wb[s][1] = *(uint32_t*)&p1;
    }
    const float cb0 = b2[2 * cc] * L2E, cb1 = b2[2 * cc + 1] * L2E;
    __syncthreads();

    uint32_t gpk[2][8];
#pragma unroll
    for (int ii = 0; ii < 2; ++ii)
#pragma unroll
        for (int s = 0; s < 4; ++s) {
            gpk[ii][2 * s]     = *(const uint32_t*)&gib_s[2 * w + ii][16 * s + 2 * cc];
            gpk[ii][2 * s + 1] = *(const uint32_t*)&gib_s[2 * w + ii][16 * s + 2 * cc + 8];
        }

    const __nv_bfloat162 zero2 = __float2bfloat162_rn(0.f);
    const int iA = i0 + 2 * w, iB = iA + 1;
    const size_t plane = (size_t)SS * SS;
    __nv_bfloat16* bgA0 = g_biasH + ((size_t)(b * HH + 2 * cc) * SS + iA) * SS;
    __nv_bfloat16* bgA1 = bgA0 + plane;
    __nv_bfloat16* bgB0 = g_biasH + ((size_t)(b * HH + 2 * cc) * SS + iB) * SS;
    __nv_bfloat16* bgB1 = bgB0 + plane;

    for (int jt = 0; jt < 4; ++jt) {
        int j0 = jt * 256;
        __syncthreads();
        for (int l = tid; l < 2048; l += 256) {
            int jr = l >> 3, c8 = (l & 7) * 8;
            uint4 v = *(const uint4*)(g_featH + ((size_t)b * SS + j0 + jr) * RH + c8);
            *(uint4*)(gjs + jr * LJS + c8) = v;
        }
        __syncthreads();

        for (int js = 0; js < 16; ++js) {
            int jb = js * 16;
            float cA[4] = {cb0, cb1, cb0, cb1};
            float cB[4] = {cb0, cb1, cb0, cb1};
            const __nv_bfloat16* gjA = gjs + (jb + r0) * LJS;
            const __nv_bfloat16* gjB = gjA + 8 * LJS;
#pragma unroll
            for (int s = 0; s < 4; ++s) {
                int ko = 16 * s + 2 * cc;
                __nv_bfloat162 gA0 = *(const __nv_bfloat162*)(gjA + ko);
                __nv_bfloat162 gA1 = *(const __nv_bfloat162*)(gjA + ko + 8);
                __nv_bfloat162 gB0 = *(const __nv_bfloat162*)(gjB + ko);
                __nv_bfloat162 gB1 = *(const __nv_bfloat162*)(gjB + ko + 8);
                {
                    __nv_bfloat162 i0v = *(const __nv_bfloat162*)&gpk[0][2 * s];
                    __nv_bfloat162 i1v = *(const __nv_bfloat162*)&gpk[0][2 * s + 1];
                    __nv_bfloat162 a0h = __hmax2(__hsub2(i0v, gA0), zero2);
                    __nv_bfloat162 a1h = __hmax2(__hsub2(i0v, gB0), zero2);
                    __nv_bfloat162 a2h = __hmax2(__hsub2(i1v, gA1), zero2);
                    __nv_bfloat162 a3h = __hmax2(__hsub2(i1v, gB1), zero2);
                    mma_bf16(cA, *(uint32_t*)&a0h, *(uint32_t*)&a1h,
                                 *(uint32_t*)&a2h, *(uint32_t*)&a3h, wb[s][0], wb[s][1]);
                }
                {
                    __nv_bfloat162 i0v = *(const __nv_bfloat162*)&gpk[1][2 * s];
                    __nv_bfloat162 i1v = *(const __nv_bfloat162*)&gpk[1][2 * s + 1];
                    __nv_bfloat162 a0h = __hmax2(__hsub2(i0v, gA0), zero2);
                    __nv_bfloat162 a1h = __hmax2(__hsub2(i0v, gB0), zero2);
                    __nv_bfloat162 a2h = __hmax2(__hsub2(i1v, gA1), zero2);
                    __nv_bfloat162 a3h = __hmax2(__hsub2(i1v, gB1), zero2);
                    mma_bf16(cB, *(uint32_t*)&a0h, *(uint32_t*)&a1h,
                                 *(uint32_t*)&a2h, *(uint32_t*)&a3h, wb[s][0], wb[s][1]);
                }
            }
            int jg = j0 + jb + r0;
            bgA0[jg]     = __float2bfloat16(cA[0]);
            bgA1[jg]     = __float2bfloat16(cA[1]);
            bgA0[jg + 8] = __float2bfloat16(cA[2]);
            bgA1[jg + 8] = __float2bfloat16(cA[3]);
            bgB0[jg]     = __float2bfloat16(cB[0]);
            bgB1[jg]     = __float2bfloat16(cB[1]);
            bgB0[jg + 8] = __float2bfloat16(cB[2]);
            bgB1[jg + 8] = __float2bfloat16(cB[3]);
        }
    }
}

// ---------------- mega_prep: transpose_w (1024) | feat (1024) ----------------
__global__ __launch_bounds__(256) void mega_prep(
    const float* __restrict__ freqs, const float* __restrict__ W1,
    const float* __restrict__ Wq, const float* __restrict__ Wk,
    const float* __restrict__ Wv, const float* __restrict__ Wo)
{
    int bid = blockIdx.x;
    if (bid < 1024) {
        __shared__ float t[32][33];
        int z = bid >> 8, rem = bid & 255;
        int bx = (rem & 15) * 32, by = (rem >> 4) * 32;
        const float* W = (z == 0) ? Wq : (z == 1) ? Wk : (z == 2) ? Wv : Wo;
        uint32_t* Wt = (uint32_t*)(g_Wt) + (size_t)z * DD * DD;
        int tx = threadIdx.x & 31, ty0 = threadIdx.x >> 5;
#pragma unroll
        for (int i = 0; i < 4; ++i)
            t[ty0 + i * 8][tx] = W[(size_t)(by + ty0 + i * 8) * DD + bx + tx];
        __syncthreads();
#pragma unroll
        for (int i = 0; i < 4; ++i)
            Wt[(size_t)(bx + ty0 + i * 8) * DD + by + tx] = f2t(t[tx][ty0 + i * 8]);
    } else {
        int idx = (bid - 1024) * 4 + (threadIdx.x >> 6);
        int k = threadIdx.x & 63;
        float f = freqs[idx];
        float L = logf(f + 1e-6f);
        g_featH[(size_t)idx * RH + k] = __float2bfloat16(f * W1[k] + L * W1[RH + k]);
    }
}

// ---------------- mega_mid: wmma_qkv (384) interleaved 3:2 with bias (256) ------------
__global__ __launch_bounds__(256) void mega_mid(
    const float* __restrict__ x,
    const float* __restrict__ bq, const float* __restrict__ bk, const float* __restrict__ bv,
    const float* __restrict__ b1, const float* __restrict__ W2, const float* __restrict__ b2)
{
    extern __shared__ uint32_t dynw[];
    int g = blockIdx.x / 5, r = blockIdx.x % 5;
    if (r < 3) {
        int q = g * 3 + r;              // 0..383
        int z = q >> 7, rem = q & 127;
        int bx = rem & 3, by = rem >> 2;
        const uint32_t* Wt = (const uint32_t*)g_Wt + (size_t)z * DD * DD;
        const float* bias = (z == 0) ? bq : (z == 1) ? bk : bv;
        __nv_bfloat16* Out = (z == 0) ? g_Q : (z == 1) ? g_K : g_Vt;
        hmma_gemm_core(dynw, (const uint32_t*)x, Wt, bias, Out,
                       (z == 0) ? 0.125f * L2E : 1.0f, nullptr,
                       (z == 2) ? 1 : 0, bx, by, 16);
    } else {
        int p = g * 2 + (r - 3);        // 0..255
        int i0 = (p & 63) * 16, b = p >> 6;
        bias_core((__nv_bfloat16*)dynw, b1, W2, b2, b, i0);
    }
}

// split-K out-proj: grid (4, 32, 2); each half does K=256 into g_part[kz]
__global__ __launch_bounds__(256) void wmma_out(const float* __restrict__ bo)
{
    extern __shared__ uint32_t dynw[];
    int kz = blockIdx.z;
    hmma_gemm_core(dynw, (const uint32_t*)g_ctx + kz * 256,
                   (const uint32_t*)g_Wt + (size_t)3 * DD * DD + kz * 256,
                   nullptr, nullptr, 1.0f, g_part + (size_t)kz * BB * SS * DD,
                   3, blockIdx.x, blockIdx.y, 8);
}

__global__ __launch_bounds__(256) void out_reduce(const float* __restrict__ bo,
                                                  float* __restrict__ out)
{
    int i = (blockIdx.x * 256 + threadIdx.x) * 4;
    float4 a = *(const float4*)(g_part + i);
    float4 b = *(const float4*)(g_part + BB * SS * DD + i);
    float4 bb = *(const float4*)(bo + (i & 511));
    *(float4*)(out + i) = make_float4(a.x + b.x + bb.x, a.y + b.y + bb.y,
                                      a.z + b.z + bb.z, a.w + b.w + bb.w);
}

// ---------------- flash attention: ldmatrix + max-free exp2 softmax -------------------
// smem bf16 words: Ps[128][36] | Ks[2][64][36] | Vt[2][64][36] | Bb[2][128][36] = 92160 B
#define LW 36
__global__ __launch_bounds__(256) void attn_mma()
{
    extern __shared__ __nv_bfloat16 smh[];
    uint32_t* PsW = (uint32_t*)smh;
    const uint32_t sbase = su32(smh);
    const uint32_t ks_b = sbase + 128 * LW * 4;
    const uint32_t vt_b = ks_b + 2 * 64 * LW * 4;
    const uint32_t bb_b = vt_b + 2 * 64 * LW * 4;

    const int it = blockIdx.x, bh = blockIdx.y;
    const int i0 = it * 128;
    const int b = bh >> 3, h = bh & 7;

    const __nv_bfloat16* Qg = g_Q + ((size_t)bh * SS + i0) * DH;
    const __nv_bfloat16* Kg = g_K + (size_t)bh * SS * DH;
    const __nv_bfloat16* Vtg = g_Vt + (size_t)bh * DH * SS;
    const __nv_bfloat16* biasg = g_biasH + (size_t)bh * SS * SS + (size_t)i0 * SS;

    const int tid = threadIdx.x;
    const int lane = tid & 31;
    const int w = tid >> 5;
    const int r0 = lane >> 2, cc = lane & 3;
    const int mrow = w * 16 + r0;

    const uint32_t klane = (uint32_t)(((lane & 7) + 8 * (lane >> 4)) * LW
                                      + 4 * ((lane >> 3) & 1)) * 4;
    const uint32_t blane = (uint32_t)((w * 16 + (lane & 7) + 8 * ((lane >> 3) & 1)) * LW
                                      + 4 * (lane >> 4)) * 4;

    {
        int row = w * 16 + (lane >> 1);
        int c0 = (lane & 1) * 32;
        const __nv_bfloat16* src = Qg + (size_t)row * DH + c0;
        uint32_t* dst = PsW + row * LW + c0 / 2;
#pragma unroll
        for (int i = 0; i < 4; ++i)
            *(uint4*)(dst + i * 4) = *(const uint4*)(src + i * 8);
    }
    __syncwarp();
    uint32_t qa[4][4];
#pragma unroll
    for (int s = 0; s < 4; ++s) {
        qa[s][0] = PsW[mrow * LW + 8 * s + cc];
        qa[s][1] = PsW[(mrow + 8) * LW + 8 * s + cc];
        qa[s][2] = PsW[mrow * LW + 8 * s + cc + 4];
        qa[s][3] = PsW[(mrow + 8) * LW + 8 * s + cc + 4];
    }
    __syncwarp();

#define STAGE(jt_, bufi) do { \
    int j0_ = (jt_) * 64; \
    for (int l = tid; l < 512; l += 256) { \
        int row_ = l >> 3, ch_ = l & 7; \
        cp16(ks_b + (uint32_t)((bufi) * 64 * LW * 4 + row_ * LW * 4 + ch_ * 16), \
             Kg + (size_t)(j0_ + row_) * DH + ch_ * 8); \
        cp16(vt_b + (uint32_t)((bufi) * 64 * LW * 4 + row_ * LW * 4 + ch_ * 16), \
             Vtg + (size_t)row_ * SS + j0_ + ch_ * 8); \
    } \
    for (int l = tid; l < 1024; l += 256) { \
        int row_ = l >> 3, ch_ = l & 7; \
        cp16(bb_b + (uint32_t)((bufi) * 128 * LW * 4 + row_ * LW * 4 + ch_ * 16), \
             biasg + (size_t)row_ * SS + j0_ + ch_ * 8); \
    } \
    CP_COMMIT(); \
} while (0)

    float l_i[2] = {0.f, 0.f};
    float co[8][4];
#pragma unroll
    for (int nt = 0; nt < 8; ++nt)
#pragma unroll
        for (int q = 0; q < 4; ++q) co[nt][q] = 0.f;

    STAGE(0, 0);

    for (int jt = 0; jt < 16; ++jt) {
        int buf = jt & 1;
        CP_WAIT0();
        __syncthreads();
        if (jt < 15) STAGE(jt + 1, buf ^ 1);

        const uint32_t kb = ks_b + (uint32_t)buf * 64 * LW * 4 + klane;
        const uint32_t vb = vt_b + (uint32_t)buf * 64 * LW * 4 + klane;
        const uint32_t bb = bb_b + (uint32_t)buf * 128 * LW * 4 + blane;

        float cs[8][4];
#pragma unroll
        for (int nt = 0; nt < 8; ++nt)
#pragma unroll
            for (int q = 0; q < 4; ++q) cs[nt][q] = 0.f;
#pragma unroll
        for (int s = 0; s < 4; ++s) {
#pragma unroll
            for (int p = 0; p < 4; ++p) {
                uint32_t b00, b01, b10, b11;
                ldsm_x4(b00, b01, b10, b11, kb + (uint32_t)(p * 16 * LW + 8 * s) * 4);
                mma_bf16(cs[2 * p],     qa[s][0], qa[s][1], qa[s][2], qa[s][3], b00, b01);
                mma_bf16(cs[2 * p + 1], qa[s][0], qa[s][1], qa[s][2], qa[s][3], b10, b11);
            }
        }

#pragma unroll
        for (int p = 0; p < 4; ++p) {
            uint32_t w0, w1, w2, w3;
            ldsm_x4(w0, w1, w2, w3, bb + (uint32_t)(8 * p) * 4);
            __nv_bfloat162 v0 = *(const __nv_bfloat162*)&w0;
            __nv_bfloat162 v1 = *(const __nv_bfloat162*)&w1;
            __nv_bfloat162 v2 = *(const __nv_bfloat162*)&w2;
            __nv_bfloat162 v3 = *(const __nv_bfloat162*)&w3;
            cs[2 * p][0]     += __bfloat162float(v0.x); cs[2 * p][1]     += __bfloat162float(v0.y);
            cs[2 * p][2]     += __bfloat162float(v1.x); cs[2 * p][3]     += __bfloat162float(v1.y);
            cs[2 * p + 1][0] += __bfloat162float(v2.x); cs[2 * p + 1][1] += __bfloat162float(v2.y);
            cs[2 * p + 1][2] += __bfloat162float(v3.x); cs[2 * p + 1][3] += __bfloat162float(v3.y);
        }

#pragma unroll
        for (int hf = 0; hf < 2; ++hf) {
            float ps = 0.f;
#pragma unroll
            for (int nt = 0; nt < 8; ++nt) {
                float p0 = ex2f(cs[nt][hf * 2]);
                float p1 = ex2f(cs[nt][hf * 2 + 1]);
                cs[nt][hf * 2] = p0; cs[nt][hf * 2 + 1] = p1;
                ps += p0 + p1;
            }
            ps += __shfl_xor_sync(0xffffffffu, ps, 1);
            ps += __shfl_xor_sync(0xffffffffu, ps, 2);
            l_i[hf] += ps;
        }

#pragma unroll
        for (int s = 0; s < 4; ++s) {
            __nv_bfloat162 h0 = __floats2bfloat162_rn(cs[2 * s][0],     cs[2 * s][1]);
            __nv_bfloat162 h1 = __floats2bfloat162_rn(cs[2 * s][2],     cs[2 * s][3]);
            __nv_bfloat162 h2 = __floats2bfloat162_rn(cs[2 * s + 1][0], cs[2 * s + 1][1]);
            __nv_bfloat162 h3 = __floats2bfloat162_rn(cs[2 * s + 1][2], cs[2 * s + 1][3]);
            uint32_t a0 = *(uint32_t*)&h0, a1 = *(uint32_t*)&h1;
            uint32_t a2 = *(uint32_t*)&h2, a3 = *(uint32_t*)&h3;
#pragma unroll
            for (int p = 0; p < 4; ++p) {
                uint32_t b00, b01, b10, b11;
                ldsm_x4(b00, b01, b10, b11, vb + (uint32_t)(p * 16 * LW + 8 * s) * 4);
                mma_bf16(co[2 * p],     a0, a1, a2, a3, b00, b01);
                mma_bf16(co[2 * p + 1], a0, a1, a2, a3, b10, b11);
            }
        }
    }
#undef STAGE

    float inv0 = 1.0f / l_i[0], inv1 = 1.0f / l_i[1];
    uint32_t* cg0 = (uint32_t*)g_ctx + ((size_t)b * SS + i0 + mrow) * DD + h * DH + cc * 2;
    uint32_t* cg1 = cg0 + 8 * DD;
#pragma unroll
    for (int nt = 0; nt < 8; ++nt) {
        *(uint2*)(cg0 + nt * 8) = make_uint2(f2t(co[nt][0] * inv0), f2t(co[nt][1] * inv0));
        *(uint2*)(cg1 + nt * 8) = make_uint2(f2t(co[nt][2] * inv1), f2t(co[nt][3] * inv1));
    }
}

// ---------------- launcher ----------------
extern "C" void kernel_launch(void* const* d_in, const int* in_sizes, int n_in,
                              void* d_out, int out_size)
{
    const float* x     = (const float*)d_in[0];
    const float* freqs = (const float*)d_in[1];
    const float* Wq = (const float*)d_in[2];  const float* bq = (const float*)d_in[3];
    const float* Wk = (const float*)d_in[4];  const float* bk = (const float*)d_in[5];
    const float* Wv = (const float*)d_in[6];  const float* bv = (const float*)d_in[7];
    const float* Wo = (const float*)d_in[8];  const float* bo = (const float*)d_in[9];
    const float* W1 = (const float*)d_in[10]; const float* b1 = (const float*)d_in[11];
    const float* W2 = (const float*)d_in[12]; const float* b2 = (const float*)d_in[13];
    float* out = (float*)d_out;

    cudaFuncSetAttribute(attn_mma, cudaFuncAttributeMaxDynamicSharedMemorySize, 92160);
    cudaFuncSetAttribute(mega_mid, cudaFuncAttributeMaxDynamicSharedMemorySize, 73728);
    cudaFuncSetAttribute(wmma_out, cudaFuncAttributeMaxDynamicSharedMemorySize, 73728);

    mega_prep<<<2048, 256>>>(freqs, W1, Wq, Wk, Wv, Wo);
    mega_mid<<<640, 256, 73728>>>(x, bq, bk, bv, b1, W2, b2);
    attn_mma<<<dim3(8, 32), 256, 92160>>>();
    wmma_out<<<dim3(4, 32, 2), 256, 73728>>>(bo);
    out_reduce<<<2048, 256>>>(bo, out);
}

// round 17
// speedup vs baseline: 1.0324x; 1.0324x over previous
#include <cuda_runtime.h>
#include <cuda_bf16.h>
#include <math.h>
#include <stdint.h>

#define BB 4
#define SS 1024
#define DD 512
#define HH 8
#define DH 64
#define RH 64
#define L2E 1.44269504f

// ---------------- static device scratch ----------------
__device__ __nv_bfloat16 g_Q[BB*HH*SS*DH];   // 4 MB (pre-scaled 1/8 * log2e)
__device__ __nv_bfloat16 g_K[BB*HH*SS*DH];   // 4 MB
__device__ __nv_bfloat16 g_Vt[BB*HH*DH*SS];  // 4 MB [b,h,d,s] (written directly by qkv)
__device__ __nv_bfloat16 g_featH[BB*SS*RH];
__device__ __nv_bfloat16 g_biasH[(size_t)BB*HH*SS*SS]; // 64 MB (bias * log2e)
__device__ float g_ctx[BB*SS*DD];        // tf32-rounded bits
__device__ float g_Wt[4*DD*DD];          // tf32-rounded W^T

// ---------------- helpers ----------------
static __device__ __forceinline__ uint32_t f2t(float x) {
    uint32_t r; asm("cvt.rna.tf32.f32 %0, %1;" : "=r"(r) : "f"(x)); return r;
}
static __device__ __forceinline__ float ex2f(float x) {
    float y; asm("ex2.approx.ftz.f32 %0, %1;" : "=f"(y) : "f"(x)); return y;
}
static __device__ __forceinline__ uint32_t su32(const void* p) {
    uint32_t a;
    asm("{ .reg .u64 t; cvta.to.shared.u64 t, %1; cvt.u32.u64 %0, t; }" : "=r"(a) : "l"(p));
    return a;
}
static __device__ __forceinline__ void cp16(uint32_t dst, const void* src) {
    asm volatile("cp.async.ca.shared.global [%0], [%1], 16;" :: "r"(dst), "l"(src) : "memory");
}
#define CP_COMMIT() asm volatile("cp.async.commit_group;" ::: "memory")
#define CP_WAIT0()  asm volatile("cp.async.wait_group 0;" ::: "memory")
#define CP_WAIT1()  asm volatile("cp.async.wait_group 1;" ::: "memory")

static __device__ __forceinline__ void ldsm_x4(
    uint32_t& r0, uint32_t& r1, uint32_t& r2, uint32_t& r3, uint32_t addr)
{
    asm volatile("ldmatrix.sync.aligned.m8n8.x4.shared.b16 {%0,%1,%2,%3}, [%4];"
                 : "=r"(r0), "=r"(r1), "=r"(r2), "=r"(r3) : "r"(addr));
}

static __device__ __forceinline__ void mma_tf32(
    float* c, uint32_t a0, uint32_t a1, uint32_t a2, uint32_t a3,
    uint32_t b0, uint32_t b1)
{
    asm volatile(
        "mma.sync.aligned.m16n8k8.row.col.f32.tf32.tf32.f32 "
        "{%0,%1,%2,%3}, {%4,%5,%6,%7}, {%8,%9}, {%0,%1,%2,%3};"
        : "+f"(c[0]), "+f"(c[1]), "+f"(c[2]), "+f"(c[3])
        : "r"(a0), "r"(a1), "r"(a2), "r"(a3), "r"(b0), "r"(b1));
}
static __device__ __forceinline__ void mma_bf16(
    float* c, uint32_t a0, uint32_t a1, uint32_t a2, uint32_t a3,
    uint32_t b0, uint32_t b1)
{
    asm volatile(
        "mma.sync.aligned.m16n8k16.row.col.f32.bf16.bf16.f32 "
        "{%0,%1,%2,%3}, {%4,%5,%6,%7}, {%8,%9}, {%0,%1,%2,%3};"
        : "+f"(c[0]), "+f"(c[1]), "+f"(c[2]), "+f"(c[3])
        : "r"(a0), "r"(a1), "r"(a2), "r"(a3), "r"(b0), "r"(b1));
}

// ---------------- tf32 HMMA GEMM core: BM=128, BK=32, 2-stage cp.async (73728 B) ------
// vmode: 0 = head-split bf16 (Q/K), 1 = transposed bf16 V, 2 = fp32 + bias
#define LDA2 36

__device__ __forceinline__ void hmma_gemm_core(
    uint32_t* __restrict__ dynsm,
    const uint32_t* __restrict__ A, const uint32_t* __restrict__ Wt,
    const float* __restrict__ bias, __nv_bfloat16* __restrict__ OutHalf,
    float hscale, float* __restrict__ OutPlain, int vmode, int bx, int by)
{
    uint32_t* As = dynsm;                    // 2 * 128 * LDA2
    uint32_t* Bs = dynsm + 2 * 128 * LDA2;   // 2 * 128 * LDA2

    const int tid = threadIdx.x;
    const int lane = tid & 31;
    const int warp = tid >> 5;
    const int wm = warp >> 2, wn = warp & 3;
    const int m0 = by * 128, n0 = bx * 128;

    const int grow = tid >> 1;
    const int gk = (tid & 1) * 16;
    const uint32_t* Arow = A + (size_t)(m0 + grow) * DD + gk;
    const uint32_t* Brow = Wt + (size_t)(n0 + grow) * DD + gk;

    const uint32_t a_sb = su32(As);
    const uint32_t b_sb = a_sb + 2 * 128 * LDA2 * 4;
    const uint32_t soff = ((uint32_t)grow * LDA2 + gk) * 4;

#define GSTAGE(k0, buf) do { \
    uint32_t o_ = (uint32_t)(buf) * (128 * LDA2 * 4) + soff; \
    cp16(a_sb + o_,      Arow + (k0)); \
    cp16(a_sb + o_ + 16, Arow + (k0) + 4); \
    cp16(a_sb + o_ + 32, Arow + (k0) + 8); \
    cp16(a_sb + o_ + 48, Arow + (k0) + 12); \
    cp16(b_sb + o_,      Brow + (k0)); \
    cp16(b_sb + o_ + 16, Brow + (k0) + 4); \
    cp16(b_sb + o_ + 32, Brow + (k0) + 8); \
    cp16(b_sb + o_ + 48, Brow + (k0) + 12); \
    CP_COMMIT(); \
} while (0)

    float c[4][4][4];
#pragma unroll
    for (int mt = 0; mt < 4; ++mt)
#pragma unroll
        for (int nt = 0; nt < 4; ++nt)
#pragma unroll
            for (int i = 0; i < 4; ++i) c[mt][nt][i] = 0.f;

    const int am = wm * 64 + (lane >> 2);
    const int ak = lane & 3;
    const int bn = wn * 32 + (lane >> 2);

    GSTAGE(0, 0);
    GSTAGE(32, 1);

    for (int it = 0; it < 16; ++it) {
        int buf = it & 1;
        if (it < 15) CP_WAIT1(); else CP_WAIT0();
        __syncthreads();
        const uint32_t* as = As + buf * 128 * LDA2;
        const uint32_t* bs = Bs + buf * 128 * LDA2;
#pragma unroll
        for (int ks = 0; ks < 4; ++ks) {
            int k0 = ks * 8;
            uint32_t bf[4][2];
#pragma unroll
            for (int nt = 0; nt < 4; ++nt) {
                bf[nt][0] = bs[(bn + nt * 8) * LDA2 + k0 + ak];
                bf[nt][1] = bs[(bn + nt * 8) * LDA2 + k0 + ak + 4];
            }
#pragma unroll
            for (int mt = 0; mt < 4; ++mt) {
                uint32_t a0 = as[(am + mt * 16) * LDA2 + k0 + ak];
                uint32_t a1 = as[(am + mt * 16 + 8) * LDA2 + k0 + ak];
                uint32_t a2 = as[(am + mt * 16) * LDA2 + k0 + ak + 4];
                uint32_t a3 = as[(am + mt * 16 + 8) * LDA2 + k0 + ak + 4];
#pragma unroll
                for (int nt = 0; nt < 4; ++nt)
                    mma_tf32(c[mt][nt], a0, a1, a2, a3, bf[nt][0], bf[nt][1]);
            }
        }
        __syncthreads();
        if (it + 2 < 16) GSTAGE((it + 2) * 32, buf);
    }

    const int crow = lane >> 2;
    const int ccol = (lane & 3) * 2;
#pragma unroll
    for (int mt = 0; mt < 4; ++mt) {
#pragma unroll
        for (int nt = 0; nt < 4; ++nt) {
            int gcol = n0 + wn * 32 + nt * 8 + ccol;
            float bxv = bias[gcol], byv = bias[gcol + 1];
#pragma unroll
            for (int half = 0; half < 2; ++half) {
                int m = m0 + wm * 64 + mt * 16 + crow + half * 8;
                float ox = c[mt][nt][half * 2 + 0] + bxv;
                float oy = c[mt][nt][half * 2 + 1] + byv;
                if (vmode == 0) {
                    int bidx = m >> 10, srow = m & 1023;
                    int h = gcol >> 6, d0 = gcol & 63;
                    __nv_bfloat162 ob = __floats2bfloat162_rn(ox * hscale, oy * hscale);
                    *(uint32_t*)(OutHalf + (((size_t)bidx * HH + h) * SS + srow) * DH + d0) =
                        *(uint32_t*)&ob;
                } else if (vmode == 1) {
                    int bidx = m >> 10, srow = m & 1023;
                    int h = gcol >> 6, d0 = gcol & 63;
                    __nv_bfloat16* base = OutHalf + ((size_t)(bidx * HH + h) * DH + d0) * SS;
                    base[srow]      = __float2bfloat16(ox);
                    base[SS + srow] = __float2bfloat16(oy);
                } else {
                    *(float2*)(OutPlain + (size_t)m * DD + gcol) = make_float2(ox, oy);
                }
            }
        }
    }
#undef GSTAGE
}

// ---------------- bias core: 16 i-rows per block; pair-packed uint32 stores -----------
#define LJS 72
__device__ __forceinline__ void bias_core(
    __nv_bfloat16* __restrict__ gjs,
    const float* __restrict__ b1, const float* __restrict__ W2, const float* __restrict__ b2,
    int b, int i0)   // i0 multiple of 16
{
    __shared__ __nv_bfloat16 gib_s[16][64];

    const int tid = threadIdx.x;
    const int lane = tid & 31;
    const int w = tid >> 5;
    const int r0 = lane >> 2;
    const int cc = lane & 3;

    for (int l = tid; l < 1024; l += 256) {
        int wi = l >> 6, k = l & 63;
        float gv = __bfloat162float(g_featH[((size_t)b * SS + i0 + wi) * RH + k]) + b1[k];
        gib_s[wi][k] = __float2bfloat16(gv);
    }

    uint32_t wb[4][2];
#pragma unroll
    for (int s = 0; s < 4; ++s) {
        __nv_bfloat162 p0 = __floats2bfloat162_rn(W2[(16 * s + 2 * cc) * HH + r0] * L2E,
                                                  W2[(16 * s + 2 * cc + 1) * HH + r0] * L2E);
        __nv_bfloat162 p1 = __floats2bfloat162_rn(W2[(16 * s + 2 * cc + 8) * HH + r0] * L2E,
                                                  W2[(16 * s + 2 * cc + 9) * HH + r0] * L2E);
        wb[s][0] = *(uint32_t*)&p0;
        wb[s][1] = *(uint32_t*)&p1;
    }
    const float cb0 = b2[2 * cc] * L2E, cb1 = b2[2 * cc + 1] * L2E;
    __syncthreads();

    uint32_t gpk[2][8];
#pragma unroll
    for (int ii = 0; ii < 2; ++ii)
#pragma unroll
        for (int s = 0; s < 4; ++s) {
            gpk[ii][2 * s]     = *(const uint32_t*)&gib_s[2 * w + ii][16 * s + 2 * cc];
            gpk[ii][2 * s + 1] = *(const uint32_t*)&gib_s[2 * w + ii][16 * s + 2 * cc + 8];
        }

    const __nv_bfloat162 zero2 = __float2bfloat162_rn(0.f);
    const int iA = i0 + 2 * w, iB = iA + 1;
    const size_t plane = (size_t)SS * SS;
    __nv_bfloat16* bgA0 = g_biasH + ((size_t)(b * HH + 2 * cc) * SS + iA) * SS;
    __nv_bfloat16* bgA1 = bgA0 + plane;
    __nv_bfloat16* bgB0 = g_biasH + ((size_t)(b * HH + 2 * cc) * SS + iB) * SS;
    __nv_bfloat16* bgB1 = bgB0 + plane;

    const bool evn = (r0 & 1) == 0;

// pair-pack across lane^4 (r0, r0+1 hold j, j+1); even-r0 lanes store aligned uint32.
#define PSTORE(val, ptr) do { \
    uint32_t m_ = (uint32_t)__bfloat16_as_ushort(__float2bfloat16(val)); \
    uint32_t o_ = __shfl_xor_sync(0xffffffffu, m_, 4); \
    if (evn) *(uint32_t*)(ptr) = m_ | (o_ << 16); \
} while (0)

    for (int jt = 0; jt < 4; ++jt) {
        int j0 = jt * 256;
        __syncthreads();
        for (int l = tid; l < 2048; l += 256) {
            int jr = l >> 3, c8 = (l & 7) * 8;
            uint4 v = *(const uint4*)(g_featH + ((size_t)b * SS + j0 + jr) * RH + c8);
            *(uint4*)(gjs + jr * LJS + c8) = v;
        }
        __syncthreads();

        for (int js = 0; js < 16; ++js) {
            int jb = js * 16;
            float cA[4] = {cb0, cb1, cb0, cb1};
            float cB[4] = {cb0, cb1, cb0, cb1};
            const __nv_bfloat16* gjA = gjs + (jb + r0) * LJS;
            const __nv_bfloat16* gjB = gjA + 8 * LJS;
#pragma unroll
            for (int s = 0; s < 4; ++s) {
                int ko = 16 * s + 2 * cc;
                __nv_bfloat162 gA0 = *(const __nv_bfloat162*)(gjA + ko);
                __nv_bfloat162 gA1 = *(const __nv_bfloat162*)(gjA + ko + 8);
                __nv_bfloat162 gB0 = *(const __nv_bfloat162*)(gjB + ko);
                __nv_bfloat162 gB1 = *(const __nv_bfloat162*)(gjB + ko + 8);
                {
                    __nv_bfloat162 i0v = *(const __nv_bfloat162*)&gpk[0][2 * s];
                    __nv_bfloat162 i1v = *(const __nv_bfloat162*)&gpk[0][2 * s + 1];
                    __nv_bfloat162 a0h = __hmax2(__hsub2(i0v, gA0), zero2);
                    __nv_bfloat162 a1h = __hmax2(__hsub2(i0v, gB0), zero2);
                    __nv_bfloat162 a2h = __hmax2(__hsub2(i1v, gA1), zero2);
                    __nv_bfloat162 a3h = __hmax2(__hsub2(i1v, gB1), zero2);
                    mma_bf16(cA, *(uint32_t*)&a0h, *(uint32_t*)&a1h,
                                 *(uint32_t*)&a2h, *(uint32_t*)&a3h, wb[s][0], wb[s][1]);
                }
                {
                    __nv_bfloat162 i0v = *(const __nv_bfloat162*)&gpk[1][2 * s];
                    __nv_bfloat162 i1v = *(const __nv_bfloat162*)&gpk[1][2 * s + 1];
                    __nv_bfloat162 a0h = __hmax2(__hsub2(i0v, gA0), zero2);
                    __nv_bfloat162 a1h = __hmax2(__hsub2(i0v, gB0), zero2);
                    __nv_bfloat162 a2h = __hmax2(__hsub2(i1v, gA1), zero2);
                    __nv_bfloat162 a3h = __hmax2(__hsub2(i1v, gB1), zero2);
                    mma_bf16(cB, *(uint32_t*)&a0h, *(uint32_t*)&a1h,
                                 *(uint32_t*)&a2h, *(uint32_t*)&a3h, wb[s][0], wb[s][1]);
                }
            }
            int jg = j0 + jb + r0;
            PSTORE(cA[0], bgA0 + jg);
            PSTORE(cA[1], bgA1 + jg);
            PSTORE(cA[2], bgA0 + jg + 8);
            PSTORE(cA[3], bgA1 + jg + 8);
            PSTORE(cB[0], bgB0 + jg);
            PSTORE(cB[1], bgB1 + jg);
            PSTORE(cB[2], bgB0 + jg + 8);
            PSTORE(cB[3], bgB1 + jg + 8);
        }
    }
#undef PSTORE
}

// ---------------- mega_prep: transpose_w (1024) | feat (1024) ----------------
__global__ __launch_bounds__(256) void mega_prep(
    const float* __restrict__ freqs, const float* __restrict__ W1,
    const float* __restrict__ Wq, const float* __restrict__ Wk,
    const float* __restrict__ Wv, const float* __restrict__ Wo)
{
    int bid = blockIdx.x;
    if (bid < 1024) {
        __shared__ float t[32][33];
        int z = bid >> 8, rem = bid & 255;
        int bx = (rem & 15) * 32, by = (rem >> 4) * 32;
        const float* W = (z == 0) ? Wq : (z == 1) ? Wk : (z == 2) ? Wv : Wo;
        uint32_t* Wt = (uint32_t*)(g_Wt) + (size_t)z * DD * DD;
        int tx = threadIdx.x & 31, ty0 = threadIdx.x >> 5;
#pragma unroll
        for (int i = 0; i < 4; ++i)
            t[ty0 + i * 8][tx] = W[(size_t)(by + ty0 + i * 8) * DD + bx + tx];
        __syncthreads();
#pragma unroll
        for (int i = 0; i < 4; ++i)
            Wt[(size_t)(bx + ty0 + i * 8) * DD + by + tx] = f2t(t[tx][ty0 + i * 8]);
    } else {
        int idx = (bid - 1024) * 4 + (threadIdx.x >> 6);
        int k = threadIdx.x & 63;
        float f = freqs[idx];
        float L = logf(f + 1e-6f);
        g_featH[(size_t)idx * RH + k] = __float2bfloat16(f * W1[k] + L * W1[RH + k]);
    }
}

// ---------------- mega_mid: wmma_qkv (384) interleaved 3:2 with bias (256) ------------
__global__ __launch_bounds__(256) void mega_mid(
    const float* __restrict__ x,
    const float* __restrict__ bq, const float* __restrict__ bk, const float* __restrict__ bv,
    const float* __restrict__ b1, const float* __restrict__ W2, const float* __restrict__ b2)
{
    extern __shared__ uint32_t dynw[];
    int g = blockIdx.x / 5, r = blockIdx.x % 5;
    if (r < 3) {
        int q = g * 3 + r;              // 0..383
        int z = q >> 7, rem = q & 127;
        int bx = rem & 3, by = rem >> 2;
        const uint32_t* Wt = (const uint32_t*)g_Wt + (size_t)z * DD * DD;
        const float* bias = (z == 0) ? bq : (z == 1) ? bk : bv;
        __nv_bfloat16* Out = (z == 0) ? g_Q : (z == 1) ? g_K : g_Vt;
        hmma_gemm_core(dynw, (const uint32_t*)x, Wt, bias, Out,
                       (z == 0) ? 0.125f * L2E : 1.0f, nullptr,
                       (z == 2) ? 1 : 0, bx, by);
    } else {
        int p = g * 2 + (r - 3);        // 0..255
        int i0 = (p & 63) * 16, b = p >> 6;
        bias_core((__nv_bfloat16*)dynw, b1, W2, b2, b, i0);
    }
}

__global__ __launch_bounds__(256) void wmma_out(const float* __restrict__ bo, float* __restrict__ out)
{
    extern __shared__ uint32_t dynw[];
    hmma_gemm_core(dynw, (const uint32_t*)g_ctx,
                   (const uint32_t*)g_Wt + (size_t)3 * DD * DD,
                   bo, nullptr, 1.0f, out, 2, blockIdx.x, blockIdx.y);
}

// ---------------- flash attention: ldmatrix + max-free exp2 softmax -------------------
// smem bf16 words: Ps[128][36] | Ks[2][64][36] | Vt[2][64][36] | Bb[2][128][36] = 92160 B
#define LW 36
__global__ __launch_bounds__(256) void attn_mma()
{
    extern __shared__ __nv_bfloat16 smh[];
    uint32_t* PsW = (uint32_t*)smh;
    const uint32_t sbase = su32(smh);
    const uint32_t ks_b = sbase + 128 * LW * 4;
    const uint32_t vt_b = ks_b + 2 * 64 * LW * 4;
    const uint32_t bb_b = vt_b + 2 * 64 * LW * 4;

    const int it = blockIdx.x, bh = blockIdx.y;
    const int i0 = it * 128;
    const int b = bh >> 3, h = bh & 7;

    const __nv_bfloat16* Qg = g_Q + ((size_t)bh * SS + i0) * DH;
    const __nv_bfloat16* Kg = g_K + (size_t)bh * SS * DH;
    const __nv_bfloat16* Vtg = g_Vt + (size_t)bh * DH * SS;
    const __nv_bfloat16* biasg = g_biasH + (size_t)bh * SS * SS + (size_t)i0 * SS;

    const int tid = threadIdx.x;
    const int lane = tid & 31;
    const int w = tid >> 5;
    const int r0 = lane >> 2, cc = lane & 3;
    const int mrow = w * 16 + r0;

    const uint32_t klane = (uint32_t)(((lane & 7) + 8 * (lane >> 4)) * LW
                                      + 4 * ((lane >> 3) & 1)) * 4;
    const uint32_t blane = (uint32_t)((w * 16 + (lane & 7) + 8 * ((lane >> 3) & 1)) * LW
                                      + 4 * (lane >> 4)) * 4;

    {
        int row = w * 16 + (lane >> 1);
        int c0 = (lane & 1) * 32;
        const __nv_bfloat16* src = Qg + (size_t)row * DH + c0;
        uint32_t* dst = PsW + row * LW + c0 / 2;
#pragma unroll
        for (int i = 0; i < 4; ++i)
            *(uint4*)(dst + i * 4) = *(const uint4*)(src + i * 8);
    }
    __syncwarp();
    uint32_t qa[4][4];
#pragma unroll
    for (int s = 0; s < 4; ++s) {
        qa[s][0] = PsW[mrow * LW + 8 * s + cc];
        qa[s][1] = PsW[(mrow + 8) * LW + 8 * s + cc];
        qa[s][2] = PsW[mrow * LW + 8 * s + cc + 4];
        qa[s][3] = PsW[(mrow + 8) * LW + 8 * s + cc + 4];
    }
    __syncwarp();

#define STAGE(jt_, bufi) do { \
    int j0_ = (jt_) * 64; \
    for (int l = tid; l < 512; l += 256) { \
        int row_ = l >> 3, ch_ = l & 7; \
        cp16(ks_b + (uint32_t)((bufi) * 64 * LW * 4 + row_ * LW * 4 + ch_ * 16), \
             Kg + (size_t)(j0_ + row_) * DH + ch_ * 8); \
        cp16(vt_b + (uint32_t)((bufi) * 64 * LW * 4 + row_ * LW * 4 + ch_ * 16), \
             Vtg + (size_t)row_ * SS + j0_ + ch_ * 8); \
    } \
    for (int l = tid; l < 1024; l += 256) { \
        int row_ = l >> 3, ch_ = l & 7; \
        cp16(bb_b + (uint32_t)((bufi) * 128 * LW * 4 + row_ * LW * 4 + ch_ * 16), \
             biasg + (size_t)row_ * SS + j0_ + ch_ * 8); \
    } \
    CP_COMMIT(); \
} while (0)

    float l_i[2] = {0.f, 0.f};
    float co[8][4];
#pragma unroll
    for (int nt = 0; nt < 8; ++nt)
#pragma unroll
        for (int q = 0; q < 4; ++q) co[nt][q] = 0.f;

    STAGE(0, 0);

    for (int jt = 0; jt < 16; ++jt) {
        int buf = jt & 1;
        CP_WAIT0();
        __syncthreads();
        if (jt < 15) STAGE(jt + 1, buf ^ 1);

        const uint32_t kb = ks_b + (uint32_t)buf * 64 * LW * 4 + klane;
        const uint32_t vb = vt_b + (uint32_t)buf * 64 * LW * 4 + klane;
        const uint32_t bb = bb_b + (uint32_t)buf * 128 * LW * 4 + blane;

        float cs[8][4];
#pragma unroll
        for (int nt = 0; nt < 8; ++nt)
#pragma unroll
            for (int q = 0; q < 4; ++q) cs[nt][q] = 0.f;
#pragma unroll
        for (int s = 0; s < 4; ++s) {
#pragma unroll
            for (int p = 0; p < 4; ++p) {
                uint32_t b00, b01, b10, b11;
                ldsm_x4(b00, b01, b10, b11, kb + (uint32_t)(p * 16 * LW + 8 * s) * 4);
                mma_bf16(cs[2 * p],     qa[s][0], qa[s][1], qa[s][2], qa[s][3], b00, b01);
                mma_bf16(cs[2 * p + 1], qa[s][0], qa[s][1], qa[s][2], qa[s][3], b10, b11);
            }
        }

#pragma unroll
        for (int p = 0; p < 4; ++p) {
            uint32_t w0, w1, w2, w3;
            ldsm_x4(w0, w1, w2, w3, bb + (uint32_t)(8 * p) * 4);
            __nv_bfloat162 v0 = *(const __nv_bfloat162*)&w0;
            __nv_bfloat162 v1 = *(const __nv_bfloat162*)&w1;
            __nv_bfloat162 v2 = *(const __nv_bfloat162*)&w2;
            __nv_bfloat162 v3 = *(const __nv_bfloat162*)&w3;
            cs[2 * p][0]     += __bfloat162float(v0.x); cs[2 * p][1]     += __bfloat162float(v0.y);
            cs[2 * p][2]     += __bfloat162float(v1.x); cs[2 * p][3]     += __bfloat162float(v1.y);
            cs[2 * p + 1][0] += __bfloat162float(v2.x); cs[2 * p + 1][1] += __bfloat162float(v2.y);
            cs[2 * p + 1][2] += __bfloat162float(v3.x); cs[2 * p + 1][3] += __bfloat162float(v3.y);
        }

#pragma unroll
        for (int hf = 0; hf < 2; ++hf) {
            float ps = 0.f;
#pragma unroll
            for (int nt = 0; nt < 8; ++nt) {
                float p0 = ex2f(cs[nt][hf * 2]);
                float p1 = ex2f(cs[nt][hf * 2 + 1]);
                cs[nt][hf * 2] = p0; cs[nt][hf * 2 + 1] = p1;
                ps += p0 + p1;
            }
            ps += __shfl_xor_sync(0xffffffffu, ps, 1);
            ps += __shfl_xor_sync(0xffffffffu, ps, 2);
            l_i[hf] += ps;
        }

#pragma unroll
        for (int s = 0; s < 4; ++s) {
            __nv_bfloat162 h0 = __floats2bfloat162_rn(cs[2 * s][0],     cs[2 * s][1]);
            __nv_bfloat162 h1 = __floats2bfloat162_rn(cs[2 * s][2],     cs[2 * s][3]);
            __nv_bfloat162 h2 = __floats2bfloat162_rn(cs[2 * s + 1][0], cs[2 * s + 1][1]);
            __nv_bfloat162 h3 = __floats2bfloat162_rn(cs[2 * s + 1][2], cs[2 * s + 1][3]);
            uint32_t a0 = *(uint32_t*)&h0, a1 = *(uint32_t*)&h1;
            uint32_t a2 = *(uint32_t*)&h2, a3 = *(uint32_t*)&h3;
#pragma unroll
            for (int p = 0; p < 4; ++p) {
                uint32_t b00, b01, b10, b11;
                ldsm_x4(b00, b01, b10, b11, vb + (uint32_t)(p * 16 * LW + 8 * s) * 4);
                mma_bf16(co[2 * p],     a0, a1, a2, a3, b00, b01);
                mma_bf16(co[2 * p + 1], a0, a1, a2, a3, b10, b11);
            }
        }
    }
#undef STAGE

    float inv0 = 1.0f / l_i[0], inv1 = 1.0f / l_i[1];
    uint32_t* cg0 = (uint32_t*)g_ctx + ((size_t)b * SS + i0 + mrow) * DD + h * DH + cc * 2;
    uint32_t* cg1 = cg0 + 8 * DD;
#pragma unroll
    for (int nt = 0; nt < 8; ++nt) {
        *(uint2*)(cg0 + nt * 8) = make_uint2(f2t(co[nt][0] * inv0), f2t(co[nt][1] * inv0));
        *(uint2*)(cg1 + nt * 8) = make_uint2(f2t(co[nt][2] * inv1), f2t(co[nt][3] * inv1));
    }
}

// ---------------- launcher ----------------
extern "C" void kernel_launch(void* const* d_in, const int* in_sizes, int n_in,
                              void* d_out, int out_size)
{
    const float* x     = (const float*)d_in[0];
    const float* freqs = (const float*)d_in[1];
    const float* Wq = (const float*)d_in[2];  const float* bq = (const float*)d_in[3];
    const float* Wk = (const float*)d_in[4];  const float* bk = (const float*)d_in[5];
    const float* Wv = (const float*)d_in[6];  const float* bv = (const float*)d_in[7];
    const float* Wo = (const float*)d_in[8];  const float* bo = (const float*)d_in[9];
    const float* W1 = (const float*)d_in[10]; const float* b1 = (const float*)d_in[11];
    const float* W2 = (const float*)d_in[12]; const float* b2 = (const float*)d_in[13];
    float* out = (float*)d_out;

    cudaFuncSetAttribute(attn_mma, cudaFuncAttributeMaxDynamicSharedMemorySize, 92160);
    cudaFuncSetAttribute(mega_mid, cudaFuncAttributeMaxDynamicSharedMemorySize, 73728);
    cudaFuncSetAttribute(wmma_out, cudaFuncAttributeMaxDynamicSharedMemorySize, 73728);

    mega_prep<<<2048, 256>>>(freqs, W1, Wq, Wk, Wv, Wo);
    mega_mid<<<640, 256, 73728>>>(x, bq, bk, bv, b1, W2, b2);
    attn_mma<<<dim3(8, 32), 256, 92160>>>();
    wmma_out<<<dim3(4, 32), 256, 73728>>>(bo, out);
}